// round 6
// baseline (speedup 1.0000x reference)
#include <cuda_runtime.h>

// ---------------------------------------------------------------------------
// QWTForward collapses to: D = bicubic_down2(image); out[q][b] = D * (S_a*S_b)
// where S_* are the sums of the 4 filter tap arrays (reference's filt(x,h)
// is exactly x * sum(h), and downsample is linear).
//
// CRITICAL: sum(gh), sum(fl), sum(fh) are analytically-zero rounding residue;
// outputs 1-3 are proportional to it. Summation must be SEQUENTIAL per filter
// (matches jnp.sum rounding; verified R1/R3/R4/R5).
//
// Body: 1 output pixel/thread (measured-best layout). Per input row, each
// thread loads only its aligned center float2; the two edge taps come from
// neighbor lanes via warp shuffle (they ARE the neighbors' center values).
// Boundary lanes (0 and 31) fall back to a clamped scalar load. This removes
// the 100%-redundant edge LDGs: ~18% fewer l1tex wavefronts, 3x fewer LDGs.
// ---------------------------------------------------------------------------

__global__ __launch_bounds__(256) void qwt_fused_kernel(
    const float* __restrict__ img,
    const float* __restrict__ gl, const float* __restrict__ gh,
    const float* __restrict__ fl, const float* __restrict__ fh,
    float* __restrict__ out, int NC, int L) {

    __shared__ float sc[16];

    // ---- scale factors: sequential add order, parallel-issued loads ----
    if (threadIdx.x < 16) {
        const int t = threadIdx.x;
        const int q = t >> 2, b = t & 3;
        const int fi = ((b & 1) << 1) | (q >> 1);
        const int si = ((b >> 1) << 1) | (q & 1);
        const float* Ff = (fi == 0) ? gl : (fi == 1) ? gh : (fi == 2) ? fl : fh;
        const float* Fs = (si == 0) ? gl : (si == 1) ? gh : (si == 2) ? fl : fh;
        float sf = 0.f, ss = 0.f;
        if (L == 30) {
            float a[30], c[30];
#pragma unroll
            for (int i = 0; i < 30; i++) { a[i] = __ldg(Ff + i); c[i] = __ldg(Fs + i); }
#pragma unroll
            for (int i = 0; i < 30; i++) { sf += a[i]; ss += c[i]; }
        } else {
            for (int i = 0; i < L; i++) { sf += Ff[i]; ss += Fs[i]; }
        }
        sc[t] = sf * ss;
    }
    __syncthreads();

    // ---- main body: one output pixel of D per thread ----
    const unsigned idx = blockIdx.x * 256u + threadIdx.x;
    const unsigned x  = idx & 255u;          // lanes consecutive in x
    const unsigned y  = (idx >> 8) & 255u;
    const unsigned nc = idx >> 16;
    const unsigned lane = threadIdx.x & 31u;

    const float* src = img + (size_t)nc * (512u * 512u);

    const float w0 = -0.09375f;
    const float w1 =  0.59375f;

    const int xc = 2 * (int)x;               // aligned center pair (xc, xc+1)
    const int xl = max(xc - 1, 0);            // only used by lane 0
    const int xr = min(xc + 2, 511);          // only used by lane 31

    const int yb = 2 * (int)y - 1;
    const int y0 = max(yb, 0);
    const int y3 = min(yb + 3, 511);
    const float* rp[4] = { src + (size_t)y0 * 512,
                           src + (size_t)(yb + 1) * 512,
                           src + (size_t)(yb + 2) * 512,
                           src + (size_t)y3 * 512 };

    float h[4];
#pragma unroll
    for (int r = 0; r < 4; r++) {
        const float2 m = __ldg((const float2*)(rp[r] + xc));
        // left tap c[2x-1] = lane-1's m.y ; right tap c[2x+2] = lane+1's m.x
        float left  = __shfl_up_sync(0xffffffffu, m.y, 1);
        float right = __shfl_down_sync(0xffffffffu, m.x, 1);
        if (lane == 0)  left  = __ldg(rp[r] + xl);
        if (lane == 31) right = __ldg(rp[r] + xr);
        h[r] = w0 * (left + right) + w1 * (m.x + m.y);
    }

    const float dval = w0 * (h[0] + h[3]) + w1 * (h[1] + h[2]);

    const unsigned n = nc / 3u;
    const unsigned c = nc - 3u * n;
    const size_t plane = 256u * 256u;
    const size_t base  = ((size_t)(n * 12u + c)) * plane + (size_t)y * 256u + x;
    const size_t QS    = (size_t)(NC / 3) * 12u * plane;  // elements per output tensor

    const float4* scv = (const float4*)sc;
#pragma unroll
    for (int q = 0; q < 4; q++) {
        const float4 sv = scv[q];
        float* o = out + base + (size_t)q * QS;
        o[0]         = dval * sv.x;
        o[3 * plane] = dval * sv.y;
        o[6 * plane] = dval * sv.z;
        o[9 * plane] = dval * sv.w;
    }
}

extern "C" void kernel_launch(void* const* d_in, const int* in_sizes, int n_in,
                              void* d_out, int out_size) {
    const float* img = (const float*)d_in[0];
    const float* gl  = (const float*)d_in[1];
    const float* gh  = (const float*)d_in[2];
    const float* fl  = (const float*)d_in[3];
    const float* fh  = (const float*)d_in[4];

    const int L  = in_sizes[1];                 // filter length (30)
    const int NC = in_sizes[0] / (512 * 512);   // N*3 = 48 channels

    const int total_threads = NC * 256 * 256;   // one per downsampled pixel
    qwt_fused_kernel<<<total_threads / 256, 256>>>(img, gl, gh, fl, fh,
                                                   (float*)d_out, NC, L);
}

// round 7
// speedup vs baseline: 1.0423x; 1.0423x over previous
#include <cuda_runtime.h>

// ---------------------------------------------------------------------------
// QWTForward collapses to: D = bicubic_down2(image); out[q][b] = D * (S_a*S_b)
// where S_* are the sums of the 4 filter tap arrays (reference's filt(x,h)
// is exactly x * sum(h), and downsample is linear).
//
// CRITICAL: sum(gh), sum(fl), sum(fh) are analytically-zero rounding residue;
// outputs 1-3 are proportional to it. Summation must be SEQUENTIAL per filter
// (matches jnp.sum rounding). Unrolling keeps the add order but issues the
// loads in parallel.
//
// Structure: tiny latency-flat scalars kernel (16 threads, unrolled) writing
// g_sc[16], then the measured-best main body (R1): 1 output pixel per thread,
// 16 scalar LDGs, 16 plain coalesced STGs. Fused variants (R3/R5/R6) all
// measured slower than this split.
// ---------------------------------------------------------------------------

__device__ float g_sc[16];

__global__ void qwt_scalars_kernel(const float* __restrict__ gl,
                                   const float* __restrict__ gh,
                                   const float* __restrict__ fl,
                                   const float* __restrict__ fh,
                                   int L) {
    const int t = threadIdx.x;
    if (t >= 16) return;
    const int q = t >> 2, b = t & 3;
    const int fi = ((b & 1) << 1) | (q >> 1);
    const int si = ((b >> 1) << 1) | (q & 1);
    const float* Ff = (fi == 0) ? gl : (fi == 1) ? gh : (fi == 2) ? fl : fh;
    const float* Fs = (si == 0) ? gl : (si == 1) ? gh : (si == 2) ? fl : fh;
    float sf = 0.f, ss = 0.f;
    if (L == 30) {
        float a[30], c[30];
#pragma unroll
        for (int i = 0; i < 30; i++) { a[i] = __ldg(Ff + i); c[i] = __ldg(Fs + i); }
#pragma unroll
        for (int i = 0; i < 30; i++) { sf += a[i]; ss += c[i]; }
    } else {
        for (int i = 0; i < L; i++) { sf += Ff[i]; ss += Fs[i]; }
    }
    g_sc[t] = sf * ss;
}

// One thread per output pixel of D (N*3 channels x 256 x 256).
// Bicubic scale-0.5 stencil, fixed fractional offset 0.5:
//   taps at input coords 2i-1 .. 2i+2, weights (-0.09375, 0.59375, 0.59375,
//   -0.09375), edge-clamped. Separable W then H (symmetric -> fold pairs).
__global__ __launch_bounds__(256) void qwt_main_kernel(
    const float* __restrict__ img, float* __restrict__ out, int NC) {
    unsigned idx = blockIdx.x * 256u + threadIdx.x;
    unsigned x  = idx & 255u;
    unsigned y  = (idx >> 8) & 255u;
    unsigned nc = idx >> 16;

    const float* src = img + (size_t)nc * (512u * 512u);

    const int xb = 2 * (int)x - 1;
    const int yb = 2 * (int)y - 1;
    const int x0 = max(xb, 0);
    const int x1 = xb + 1;
    const int x2 = xb + 2;
    const int x3 = min(xb + 3, 511);
    const int y0 = max(yb, 0);
    const int y3 = min(yb + 3, 511);

    const float w0 = -0.09375f;
    const float w1 =  0.59375f;

    const float* r0 = src + (size_t)y0 * 512;
    const float* r1 = src + (size_t)(yb + 1) * 512;
    const float* r2 = src + (size_t)(yb + 2) * 512;
    const float* r3 = src + (size_t)y3 * 512;

    float h0 = w0 * (__ldg(r0 + x0) + __ldg(r0 + x3)) + w1 * (__ldg(r0 + x1) + __ldg(r0 + x2));
    float h1 = w0 * (__ldg(r1 + x0) + __ldg(r1 + x3)) + w1 * (__ldg(r1 + x1) + __ldg(r1 + x2));
    float h2 = w0 * (__ldg(r2 + x0) + __ldg(r2 + x3)) + w1 * (__ldg(r2 + x1) + __ldg(r2 + x2));
    float h3 = w0 * (__ldg(r3 + x0) + __ldg(r3 + x3)) + w1 * (__ldg(r3 + x1) + __ldg(r3 + x2));

    const float dval = w0 * (h0 + h3) + w1 * (h1 + h2);

    const unsigned n = nc / 3u;
    const unsigned c = nc - 3u * n;
    const size_t plane = 256u * 256u;
    const size_t base  = ((size_t)(n * 12u + c)) * plane + (size_t)y * 256u + x;
    const size_t QS    = (size_t)(NC / 3) * 12u * plane;  // elements per output tensor

    const float4* scv = (const float4*)g_sc;
#pragma unroll
    for (int q = 0; q < 4; q++) {
        const float4 sv = scv[q];
        float* o = out + base + (size_t)q * QS;
        o[0]         = dval * sv.x;
        o[3 * plane] = dval * sv.y;
        o[6 * plane] = dval * sv.z;
        o[9 * plane] = dval * sv.w;
    }
}

extern "C" void kernel_launch(void* const* d_in, const int* in_sizes, int n_in,
                              void* d_out, int out_size) {
    const float* img = (const float*)d_in[0];
    const float* gl  = (const float*)d_in[1];
    const float* gh  = (const float*)d_in[2];
    const float* fl  = (const float*)d_in[3];
    const float* fh  = (const float*)d_in[4];

    const int L  = in_sizes[1];                 // filter length (30)
    const int NC = in_sizes[0] / (512 * 512);   // N*3 = 48 channels

    qwt_scalars_kernel<<<1, 32>>>(gl, gh, fl, fh, L);

    const int total_threads = NC * 256 * 256;   // one per downsampled pixel
    qwt_main_kernel<<<total_threads / 256, 256>>>(img, (float*)d_out, NC);
}